// round 7
// baseline (speedup 1.0000x reference)
#include <cuda_runtime.h>

// y (4,1,512,512) fp32; BINS=256, VMIN=0, VMAX=1, SIGMA=30.
// One persistent kernel, 148 CTAs (single wave):
//   Phase 1: per-pixel RED.E.ADD into global 4096-bin fine histogram per batch
//   (global integer atomics: exact + order-independent). K sigmoid-diff table
//   built concurrently.
//   [grid barrier]
//   Phase 2: 128 CTAs correlate counts with K (8 output bins each), convert
//   per-CTA partial entropy to 2^-50 fixed point, single integer atomicAdd.
//   Last-done CTA computes 1/d and re-zeros state for graph replay.

#define NB 4
#define HW 262144
#define FINE 4096
#define BINS 256
#define GRID 148
#define CPB 37                     // histogram CTAs per batch
#define F4B 65536                  // float4 per batch
#define TBL 8192                   // K table alloc (8176 valid)
#define TOFF 4080
#define KSTEP (30.0f/4096.0f)
#define NTHR 1024
#define FXSCALE 1125899906842624.0          /* 2^50  */
#define FXINV   8.881784197001252e-16       /* 2^-50 */

__device__ unsigned int       g_nu[NB][FINE];  // zero at load; re-zeroed each call
__device__ float              g_K[TBL];
__device__ unsigned long long g_dacc;          // fixed-point entropy accumulator
__device__ unsigned int       g_done;
__device__ unsigned int       g_bar;

// sigmoid for t <= 0 (no cancellation)
__device__ __forceinline__ float sneg(float t) {
    float e = expf(t);
    return e / (1.0f + e);
}
// sigma(a1) - sigma(a2), a1 > a2, cancellation-safe
__device__ __forceinline__ float sigdiff(float a1, float a2) {
    if (a2 >= 0.0f) return sneg(-a2) - sneg(-a1);
    if (a1 <= 0.0f) return sneg(a1) - sneg(a2);
    return (1.0f - sneg(-a1)) - sneg(a2);
}

// Self-resetting two-phase counting grid barrier (re-entrant across replays).
__device__ __forceinline__ void gridbar() {
    __syncthreads();
    if (threadIdx.x == 0) {
        __threadfence();
        atomicAdd(&g_bar, 1u);
        while (*((volatile unsigned int*)&g_bar) < (unsigned)GRID) { }
        unsigned int old = atomicAdd(&g_bar, 1u);
        if (old == 2u * GRID - 1u) atomicExch(&g_bar, 0u);
        __threadfence();
    }
    __syncthreads();
}

__global__ void __launch_bounds__(NTHR, 1) k_fused(const float* __restrict__ y,
                                                   float* __restrict__ out) {
    __shared__ float snf[FINE];
    __shared__ float s_part[8][4];
    __shared__ float s_term[8];
    __shared__ int   s_last;

    const int tid = threadIdx.x;
    const int cta = blockIdx.x;

    // ---- K table: 56 entries per CTA (148*56 >= 8192); overlaps phase 1 ----
    if (tid < 56) {
        int idx = cta * 56 + tid;
        if (idx < TBL) {
            float v = 0.0f;
            if (idx < TOFF + FINE) {
                float q = (float)(idx - TOFF);
                v = sigdiff(KSTEP * (q + 0.5f), KSTEP * (q - 15.5f));
            }
            g_K[idx] = v;
        }
    }

    // ---- Phase 1: direct global RED histogram (no shared hist, no merge) ----
    {
        int b     = cta / CPB;                 // batch 0..3 (37 CTAs each)
        int local = cta - b * CPB;
        // split 65536 float4 over 37 CTAs: 9 CTAs get 1772, 28 get 1771
        int base  = b * F4B + local * 1771 + min(local, 9);
        int len   = 1771 + (local < 9 ? 1 : 0);

        const float4* yp = (const float4*)y;
        unsigned int* nb = g_nu[b];

        float4 v0 = yp[base + tid];
        bool   has2 = (tid + 1024) < len;
        float4 v1;
        if (has2) v1 = yp[base + 1024 + tid];

        atomicAdd(&nb[min(max((int)(v0.x * 4096.0f), 0), 4095)], 1u);
        atomicAdd(&nb[min(max((int)(v0.y * 4096.0f), 0), 4095)], 1u);
        atomicAdd(&nb[min(max((int)(v0.z * 4096.0f), 0), 4095)], 1u);
        atomicAdd(&nb[min(max((int)(v0.w * 4096.0f), 0), 4095)], 1u);
        if (has2) {
            atomicAdd(&nb[min(max((int)(v1.x * 4096.0f), 0), 4095)], 1u);
            atomicAdd(&nb[min(max((int)(v1.y * 4096.0f), 0), 4095)], 1u);
            atomicAdd(&nb[min(max((int)(v1.z * 4096.0f), 0), 4095)], 1u);
            atomicAdd(&nb[min(max((int)(v1.w * 4096.0f), 0), 4095)], 1u);
        }
    }

    gridbar();

    // ---- Phase 2: 128 row-CTAs (8 output bins each); rest exit ----
    if (cta >= 128) return;

    const int b = cta >> 5;                    // batch
    const int g = cta & 31;                    // bin group within batch
    {
        uint4 u = ((const uint4*)g_nu[b])[tid];
        ((float4*)snf)[tid] = make_float4((float)u.x, (float)u.y,
                                          (float)u.z, (float)u.w);
    }
    __syncthreads();

    {
        int w = tid >> 5, lane = tid & 31;
        int r = w >> 2, q = w & 3;
        int i = g * 8 + r;                     // output bin 0..255
        const float*  np = snf + q * 1024;
        const float4* Kp = (const float4*)(g_K + (TOFF - 16 * i) + q * 1024);

        float4 acc = make_float4(0.f, 0.f, 0.f, 0.f);
        #pragma unroll
        for (int it = 0; it < 8; it++) {
            int m = it * 128 + lane * 4;
            float4 nv = *(const float4*)(np + m);
            float4 kv = __ldg(Kp + (m >> 2));
            acc.x += nv.x * kv.x; acc.y += nv.y * kv.y;
            acc.z += nv.z * kv.z; acc.w += nv.w * kv.w;
        }
        float a = (acc.x + acc.y) + (acc.z + acc.w);
        #pragma unroll
        for (int off = 16; off; off >>= 1)
            a += __shfl_down_sync(0xffffffffu, a, off);
        if (lane == 0) s_part[r][q] = a;
    }
    __syncthreads();

    if (tid < 8) {
        float h  = (s_part[tid][0] + s_part[tid][1]) + (s_part[tid][2] + s_part[tid][3]);
        float pr = h * (1.0f / (float)HW) + 1e-6f;
        s_term[tid] = -pr * logf(pr);
    }
    __syncthreads();

    if (tid == 0) {
        float s = ((s_term[0] + s_term[1]) + (s_term[2] + s_term[3]))
                + ((s_term[4] + s_term[5]) + (s_term[6] + s_term[7]));
        unsigned long long qv = (unsigned long long)((double)s * FXSCALE + 0.5);
        atomicAdd(&g_dacc, qv);
        __threadfence();
        unsigned int old = atomicAdd(&g_done, 1u);
        s_last = (old == 127u);
    }
    __syncthreads();

    // ---- Tail: elected last CTA finalizes + resets state for replay ----
    if (s_last) {
        #pragma unroll
        for (int k = 0; k < (NB * FINE) / NTHR; k++)
            ((unsigned int*)g_nu)[tid + k * NTHR] = 0u;
        if (tid == 0) {
            unsigned long long tot = atomicExch(&g_dacc, 0ULL);
            atomicExch(&g_done, 0u);
            out[0] = (float)(1.0 / ((double)tot * FXINV));
        }
    }
}

extern "C" void kernel_launch(void* const* d_in, const int* in_sizes, int n_in,
                              void* d_out, int out_size) {
    (void)in_sizes; (void)n_in; (void)out_size;
    k_fused<<<GRID, NTHR>>>((const float*)d_in[0], (float*)d_out);
}

// round 8
// speedup vs baseline: 2.0825x; 2.0825x over previous
#include <cuda_runtime.h>

// y (4,1,512,512) fp32; BINS=256, VMIN=0, VMAX=1, SIGMA=30.
// One persistent kernel, 148 CTAs (single wave):
//  Phase 1: per-CTA SHARED 2048-bin fine histogram (shared atomics = proven
//           fastest path; global RED direct was 2x slower in R7), then merge
//           nonzero counts into global integer bins via RED (exact).
//  [grid barrier]
//  Phase 2: 128 CTAs correlate counts with sigmoid-difference table K
//           (8 output bins each), fixed-point atomicAdd of partial entropy;
//           last-done CTA computes 1/d and re-zeros state for graph replay.

#define NB 4
#define HW 262144
#define FINE 2048
#define BINS 256
#define GRID 148
#define CPB 37                     // histogram CTAs per batch
#define F4B 65536                  // float4 per batch
#define TBL 4096                   // K table alloc (4088 valid)
#define TOFF 2040                  // K index offset: q = idx - TOFF
#define KSTEP (30.0f/2048.0f)
#define NTHR 1024
#define FXSCALE 1125899906842624.0          /* 2^50  */
#define FXINV   8.881784197001252e-16       /* 2^-50 */

__device__ unsigned int       g_nu[NB][FINE];  // zero at load; re-zeroed each call
__device__ float              g_K[TBL];
__device__ unsigned long long g_dacc;          // fixed-point entropy accumulator
__device__ unsigned int       g_done;
__device__ unsigned int       g_bar;

// sigmoid for t <= 0 (no cancellation)
__device__ __forceinline__ float sneg(float t) {
    float e = expf(t);
    return e / (1.0f + e);
}
// sigma(a1) - sigma(a2), a1 > a2, cancellation-safe
__device__ __forceinline__ float sigdiff(float a1, float a2) {
    if (a2 >= 0.0f) return sneg(-a2) - sneg(-a1);
    if (a1 <= 0.0f) return sneg(a1) - sneg(a2);
    return (1.0f - sneg(-a1)) - sneg(a2);
}

// Self-resetting two-phase counting grid barrier (re-entrant across replays).
__device__ __forceinline__ void gridbar() {
    __syncthreads();
    if (threadIdx.x == 0) {
        __threadfence();
        atomicAdd(&g_bar, 1u);
        while (*((volatile unsigned int*)&g_bar) < (unsigned)GRID) { }
        unsigned int old = atomicAdd(&g_bar, 1u);
        if (old == 2u * GRID - 1u) atomicExch(&g_bar, 0u);
        __threadfence();
    }
    __syncthreads();
}

__global__ void __launch_bounds__(NTHR, 1) k_fused(const float* __restrict__ y,
                                                   float* __restrict__ out) {
    __shared__ unsigned int shh[FINE];       // phase1 hist; phase2 reused as float n
    __shared__ float s_part[8][4];
    __shared__ float s_term[8];
    __shared__ int   s_last;

    const int tid = threadIdx.x;
    const int cta = blockIdx.x;

    // ---- K table: 28 entries per CTA (148*28 >= 4096); overlaps phase 1 ----
    if (tid < 28) {
        int idx = cta * 28 + tid;
        if (idx < TBL) {
            float v = 0.0f;
            if (idx < TOFF + FINE) {           // 4088 valid
                float q = (float)(idx - TOFF);
                v = sigdiff(KSTEP * (q + 0.5f), KSTEP * (q - 7.5f));
            }
            g_K[idx] = v;
        }
    }

    // ---- Phase 1: per-CTA shared fine histogram ----
    shh[tid] = 0u;
    shh[tid + 1024] = 0u;
    __syncthreads();

    int b, nonzero_lo, nonzero_hi;
    {
        b         = cta / CPB;                 // batch 0..3 (37 CTAs each)
        int local = cta - b * CPB;
        // split 65536 float4 over 37 CTAs: 9 CTAs get 1772, 28 get 1771
        int base  = b * F4B + local * 1771 + min(local, 9);
        int len   = 1771 + (local < 9 ? 1 : 0);

        const float4* yp = (const float4*)y;

        float4 v0 = yp[base + tid];
        bool   has2 = (tid + 1024) < len;
        float4 v1;
        if (has2) v1 = yp[base + 1024 + tid];

        atomicAdd(&shh[min(max((int)(v0.x * 2048.0f), 0), 2047)], 1u);
        atomicAdd(&shh[min(max((int)(v0.y * 2048.0f), 0), 2047)], 1u);
        atomicAdd(&shh[min(max((int)(v0.z * 2048.0f), 0), 2047)], 1u);
        atomicAdd(&shh[min(max((int)(v0.w * 2048.0f), 0), 2047)], 1u);
        if (has2) {
            atomicAdd(&shh[min(max((int)(v1.x * 2048.0f), 0), 2047)], 1u);
            atomicAdd(&shh[min(max((int)(v1.y * 2048.0f), 0), 2047)], 1u);
            atomicAdd(&shh[min(max((int)(v1.z * 2048.0f), 0), 2047)], 1u);
            atomicAdd(&shh[min(max((int)(v1.w * 2048.0f), 0), 2047)], 1u);
        }
    }
    __syncthreads();

    // merge nonzero counts into global integer bins (exact, order-independent)
    if (tid < FINE) {                            // 2048 threads? no: 1024, 2 each
    }
    {
        unsigned int c0 = shh[tid];
        unsigned int c1 = shh[tid + 1024];
        if (c0) atomicAdd(&g_nu[b][tid], c0);
        if (c1) atomicAdd(&g_nu[b][tid + 1024], c1);
    }

    gridbar();

    // ---- Phase 2: 128 row-CTAs (8 output bins each); rest exit ----
    if (cta >= 128) return;

    const int bb = cta >> 5;                   // batch
    const int g  = cta & 31;                   // bin group within batch
    float* snf = (float*)shh;
    if (tid < FINE / 4) {
        uint4 u = ((const uint4*)g_nu[bb])[tid];
        ((float4*)snf)[tid] = make_float4((float)u.x, (float)u.y,
                                          (float)u.z, (float)u.w);
    }
    __syncthreads();

    {
        int w = tid >> 5, lane = tid & 31;
        int r = w >> 2, q = w & 3;
        int i = g * 8 + r;                     // output bin 0..255
        const float*  np = snf + q * 512;
        const float4* Kp = (const float4*)(g_K + (TOFF - 8 * i) + q * 512);

        float4 acc = make_float4(0.f, 0.f, 0.f, 0.f);
        #pragma unroll
        for (int it = 0; it < 4; it++) {       // 4 * 128 = 512 taps per warp
            int m = it * 128 + lane * 4;
            float4 nv = *(const float4*)(np + m);
            float4 kv = __ldg(Kp + (m >> 2));
            acc.x += nv.x * kv.x; acc.y += nv.y * kv.y;
            acc.z += nv.z * kv.z; acc.w += nv.w * kv.w;
        }
        float a = (acc.x + acc.y) + (acc.z + acc.w);
        #pragma unroll
        for (int off = 16; off; off >>= 1)
            a += __shfl_down_sync(0xffffffffu, a, off);
        if (lane == 0) s_part[r][q] = a;
    }
    __syncthreads();

    if (tid < 8) {
        float h  = (s_part[tid][0] + s_part[tid][1]) + (s_part[tid][2] + s_part[tid][3]);
        float pr = h * (1.0f / (float)HW) + 1e-6f;
        s_term[tid] = -pr * logf(pr);
    }
    __syncthreads();

    if (tid == 0) {
        float s = ((s_term[0] + s_term[1]) + (s_term[2] + s_term[3]))
                + ((s_term[4] + s_term[5]) + (s_term[6] + s_term[7]));
        unsigned long long qv = (unsigned long long)((double)s * FXSCALE + 0.5);
        atomicAdd(&g_dacc, qv);
        __threadfence();
        unsigned int old = atomicAdd(&g_done, 1u);
        s_last = (old == 127u);
    }
    __syncthreads();

    // ---- Tail: elected last CTA finalizes + resets state for replay ----
    if (s_last) {
        #pragma unroll
        for (int k = 0; k < (NB * FINE) / NTHR; k++)   // 8192 / 1024 = 8
            ((unsigned int*)g_nu)[tid + k * NTHR] = 0u;
        if (tid == 0) {
            unsigned long long tot = atomicExch(&g_dacc, 0ULL);
            atomicExch(&g_done, 0u);
            out[0] = (float)(1.0 / ((double)tot * FXINV));
        }
    }
}

extern "C" void kernel_launch(void* const* d_in, const int* in_sizes, int n_in,
                              void* d_out, int out_size) {
    (void)in_sizes; (void)n_in; (void)out_size;
    k_fused<<<GRID, NTHR>>>((const float*)d_in[0], (float*)d_out);
}